// round 15
// baseline (speedup 1.0000x reference)
#include <cuda_runtime.h>

// Adder2D: out[n,co,h,w] = -sum_{ci,kh,kw} |x_pad - w|
// R15 = R14 data path (prepass-packed ci-pairs, cp.async 16B double-buffered,
// CO_T=8, FADD2 diff -> 2xLOP3 abs -> FADD2 acc) with a SMALLER block:
// 8 ci per block (SLICE_Q=2 x NSLICE=2), launch_bounds(128,10) -> 40 warps/SM,
// grid 4096 -> 2.7 waves at 10 blocks/SM (90% wave utilization).

#define CI_   64
#define CO_   64
#define H_    32
#define W_    32
#define NMAX_ 16

#define CO_T     8
#define TILE_H   8      // thread owns rows 2ty, 2ty+1
#define SLICE_Q  2      // ci-pairs per slice (= 4 ci)
#define NSLICE   2      // slices per block (8 ci) -> ci-split x8
#define THREADS  128

#define XS_ROWS  10     // TILE_H + 2
#define XS_COLS  34     // W + 2
#define PLANE    (XS_ROWS * XS_COLS)          // 340 u64
#define BUFSZ    (SLICE_Q * PLANE)            // 680 u64 per slice buffer

typedef unsigned long long u64;

// packed x scratch: [n][q=ci/2][h][w] = pack(x[2q], x[2q+1]) -- 4MB
__device__ u64 xpack_buf[NMAX_ * (CI_ / 2) * H_ * W_];

__device__ __forceinline__ u64 f2add(u64 a, u64 b) {
    u64 r;
    asm("add.rn.f32x2 %0, %1, %2;" : "=l"(r) : "l"(a), "l"(b));
    return r;
}

__device__ __forceinline__ u64 packff(float lo, float hi) {
    u64 r;
    asm("mov.b64 %0, {%1, %2};" : "=l"(r) : "f"(lo), "f"(hi));
    return r;
}

__device__ __forceinline__ float u64lo(u64 v) {
    return __uint_as_float((unsigned int)(v & 0xffffffffu));
}
__device__ __forceinline__ float u64hi(u64 v) {
    return __uint_as_float((unsigned int)(v >> 32));
}

__device__ __forceinline__ void cp_async16(unsigned int smem_addr, const void* gptr) {
    asm volatile("cp.async.ca.shared.global [%0], [%1], 16;\n"
                 :: "r"(smem_addr), "l"(gptr));
}

// ---------------- prepass: pack adjacent ci planes ----------------
__global__ void __launch_bounds__(256)
pack_kernel(const float* __restrict__ x, int total)
{
    const int i = blockIdx.x * 256 + threadIdx.x;
    if (i >= total) return;
    const int hw = i & (H_ * W_ - 1);
    const int q  = (i >> 10) & (CI_ / 2 - 1);
    const int n  = i >> 15;
    const float* base = x + ((size_t)n * CI_ + 2 * q) * (H_ * W_) + hw;
    xpack_buf[i] = packff(base[0], base[H_ * W_]);
}

// ---------------- main kernel ----------------
__global__ void __launch_bounds__(THREADS, 10)
adder2d_kernel(const float* __restrict__ w,
               float* __restrict__ out)
{
    // packed x planes; LEAD=1 so interior (col>=1) 16B chunks are aligned
    __shared__ u64 xq[2 * BUFSZ + 2];
    // ci-pair packed negated weights: [slice][q][tap][co], co contiguous, 16B aligned
    __shared__ __align__(16) u64 ws2[NSLICE][SLICE_Q][9][CO_T];

    const int tid = threadIdx.x;
    const int tx  = tid & 31;
    const int ty  = tid >> 5;
    const int h0  = blockIdx.x * TILE_H;
    const int co0 = blockIdx.y * CO_T;
    const int n   = blockIdx.z >> 3;
    const int q0  = (blockIdx.z & 7) * (SLICE_Q * NSLICE);   // first ci-pair index

    const u64* xp = xpack_buf + (size_t)n * (CI_ / 2) * (H_ * W_);

    // ---- zero halo (cols 0/33 per row; full rows where gh out of range) ----
    for (int i = tid; i < NSLICE * SLICE_Q * XS_ROWS; i += THREADS) {   // 40 rows
        const int s  = i / (SLICE_Q * XS_ROWS);
        const int j  = i - s * (SLICE_Q * XS_ROWS);
        const int ql = j / XS_ROWS;
        const int r  = j - ql * XS_ROWS;
        u64* row = &xq[1 + s * BUFSZ + ql * PLANE + r * XS_COLS];
        const int gh = h0 + r - 1;
        if ((unsigned)gh >= (unsigned)H_) {
            #pragma unroll
            for (int c = 0; c < XS_COLS; ++c) row[c] = 0ull;
        } else {
            row[0] = 0ull;
            row[XS_COLS - 1] = 0ull;
        }
    }

    // ---- issue cp.async for BOTH slices (16B chunks = 2 packed pairs) ----
    #pragma unroll
    for (int s = 0; s < NSLICE; ++s) {
        // 2 planes x 10 rows x 16 chunks = 320 ops per slice
        for (int i = tid; i < SLICE_Q * XS_ROWS * 16; i += THREADS) {
            const int ql = i / (XS_ROWS * 16);
            const int j  = i - ql * (XS_ROWS * 16);
            const int r  = j / 16;
            const int k  = j - r * 16;
            const int gh = h0 + r - 1;
            if ((unsigned)gh < (unsigned)H_) {
                u64* dst = &xq[2 + s * BUFSZ + ql * PLANE + r * XS_COLS + 2 * k];
                unsigned int da = (unsigned int)__cvta_generic_to_shared(dst);
                cp_async16(da, xp + (size_t)(q0 + s * SLICE_Q + ql) * (H_ * W_) + gh * W_ + 2 * k);
            }
        }
        asm volatile("cp.async.commit_group;\n" ::: "memory");
    }

    // ---- stage w for both slices (overlaps cp.async latency) ----
    for (int i = tid; i < NSLICE * SLICE_Q * 9 * CO_T; i += THREADS) {   // 288
        const int s  = i / (SLICE_Q * 9 * CO_T);
        const int r1 = i - s * (SLICE_Q * 9 * CO_T);
        const int ql = r1 / (9 * CO_T);
        const int r2 = r1 - ql * (9 * CO_T);
        const int tap = r2 / CO_T;
        const int co  = r2 - tap * CO_T;
        const int cib = 2 * (q0 + s * SLICE_Q + ql);
        const float w0 = w[(co0 + co) * (CI_ * 9) + (cib + 0) * 9 + tap];
        const float w1 = w[(co0 + co) * (CI_ * 9) + (cib + 1) * 9 + tap];
        ws2[s][ql][tap][co] = packff(-w0, -w1);
    }

    // accumulators: [pixel-row(2)][co(8)], halves = even/odd ci partial sums
    u64 acc[2][CO_T];
    #pragma unroll
    for (int p = 0; p < 2; ++p)
        #pragma unroll
        for (int co = 0; co < CO_T; ++co) acc[p][co] = 0ull;

    const int px = tx;
    const int ry = 2 * ty;

    #pragma unroll
    for (int s = 0; s < NSLICE; ++s) {
        if (s == 0) asm volatile("cp.async.wait_group 1;\n" ::: "memory");
        else        asm volatile("cp.async.wait_group 0;\n" ::: "memory");
        __syncthreads();

        const int xb = 1 + s * BUFSZ;
        #pragma unroll
        for (int ql = 0; ql < SLICE_Q; ++ql) {
            const int pb = xb + ql * PLANE;
            #pragma unroll
            for (int kh = 0; kh < 3; ++kh) {
                #pragma unroll
                for (int kw = 0; kw < 3; ++kw) {
                    const u64 x0 = xq[pb + (ry + 0 + kh) * XS_COLS + px + kw];  // LDS.64
                    const u64 x1 = xq[pb + (ry + 1 + kh) * XS_COLS + px + kw];  // LDS.64
                    const int tap = kh * 3 + kw;
                    #pragma unroll
                    for (int cp = 0; cp < CO_T / 2; ++cp) {
                        const ulonglong2 wv = *(const ulonglong2*)&ws2[s][ql][tap][2 * cp];
                        u64 d0 = f2add(x0, wv.x);               // fma pipe
                        u64 d1 = f2add(x1, wv.x);
                        d0 &= 0x7fffffff7fffffffULL;            // alu pipe (2x LOP3)
                        d1 &= 0x7fffffff7fffffffULL;
                        acc[0][2 * cp + 0] = f2add(acc[0][2 * cp + 0], d0);
                        acc[1][2 * cp + 0] = f2add(acc[1][2 * cp + 0], d1);
                        u64 e0 = f2add(x0, wv.y);
                        u64 e1 = f2add(x1, wv.y);
                        e0 &= 0x7fffffff7fffffffULL;
                        e1 &= 0x7fffffff7fffffffULL;
                        acc[0][2 * cp + 1] = f2add(acc[0][2 * cp + 1], e0);
                        acc[1][2 * cp + 1] = f2add(acc[1][2 * cp + 1], e1);
                    }
                }
            }
        }
    }

    // ---- epilogue: horizontal add (even+odd ci), atomic combine (out pre-zeroed) ----
    #pragma unroll
    for (int co = 0; co < CO_T; ++co) {
        #pragma unroll
        for (int p = 0; p < 2; ++p) {
            const float ssum = u64lo(acc[p][co]) + u64hi(acc[p][co]);
            const int h = h0 + ry + p;
            atomicAdd(&out[(((size_t)n * CO_ + (co0 + co)) * H_ + h) * W_ + px], -ssum);
        }
    }
}

extern "C" void kernel_launch(void* const* d_in, const int* in_sizes, int n_in,
                              void* d_out, int out_size)
{
    const float* x = (const float*)d_in[0];
    const float* w = (const float*)d_in[1];
    float* out = (float*)d_out;

    const int N = in_sizes[0] / (CI_ * H_ * W_);   // 16
    const int total = N * (CI_ / 2) * H_ * W_;     // 524288 packed pairs

    cudaMemsetAsync(d_out, 0, (size_t)out_size * sizeof(float));
    pack_kernel<<<(total + 255) / 256, 256>>>(x, total);

    dim3 grid(H_ / TILE_H, CO_ / CO_T, N * 8);     // (4, 8, 128) = 4096 blocks
    adder2d_kernel<<<grid, THREADS>>>(w, out);
}

// round 16
// speedup vs baseline: 1.1258x; 1.1258x over previous
#include <cuda_runtime.h>

// Adder2D: out[n,co,h,w] = -sum_{ci,kh,kw} |x_pad - w|
// R16 = R14 data path (prepass-packed ci-pairs, cp.async 16B, CO_T=8,
// FADD2 diff -> 2xLOP3 abs -> FADD2 acc) restructured for ONE WAVE:
// grid 1024 blocks (ci-split x2), each block pipelines 4 slices of 8 ci
// through 2 smem buffers (issue s+2 after computing s). Zero wave tail.

#define CI_   64
#define CO_   64
#define H_    32
#define W_    32
#define NMAX_ 16

#define CO_T     8
#define TILE_H   8      // thread owns rows 2ty, 2ty+1
#define SLICE_Q  4      // ci-pairs per slice (= 8 ci)
#define NSLICE   4      // slices per block (32 ci) -> ci-split x2
#define THREADS  128

#define XS_ROWS  10     // TILE_H + 2
#define XS_COLS  34     // W + 2
#define PLANE    (XS_ROWS * XS_COLS)          // 340 u64
#define BUFSZ    (SLICE_Q * PLANE)            // 1360 u64 per buffer

typedef unsigned long long u64;

// packed x scratch: [n][q=ci/2][h][w] = pack(x[2q], x[2q+1]) -- 4MB
__device__ u64 xpack_buf[NMAX_ * (CI_ / 2) * H_ * W_];

__device__ __forceinline__ u64 f2add(u64 a, u64 b) {
    u64 r;
    asm("add.rn.f32x2 %0, %1, %2;" : "=l"(r) : "l"(a), "l"(b));
    return r;
}

__device__ __forceinline__ u64 packff(float lo, float hi) {
    u64 r;
    asm("mov.b64 %0, {%1, %2};" : "=l"(r) : "f"(lo), "f"(hi));
    return r;
}

__device__ __forceinline__ float u64lo(u64 v) {
    return __uint_as_float((unsigned int)(v & 0xffffffffu));
}
__device__ __forceinline__ float u64hi(u64 v) {
    return __uint_as_float((unsigned int)(v >> 32));
}

__device__ __forceinline__ void cp_async16(unsigned int smem_addr, const void* gptr) {
    asm volatile("cp.async.ca.shared.global [%0], [%1], 16;\n"
                 :: "r"(smem_addr), "l"(gptr));
}

// ---------------- prepass: pack adjacent ci planes ----------------
__global__ void __launch_bounds__(256)
pack_kernel(const float* __restrict__ x, int total)
{
    const int i = blockIdx.x * 256 + threadIdx.x;
    if (i >= total) return;
    const int hw = i & (H_ * W_ - 1);
    const int q  = (i >> 10) & (CI_ / 2 - 1);
    const int n  = i >> 15;
    const float* base = x + ((size_t)n * CI_ + 2 * q) * (H_ * W_) + hw;
    xpack_buf[i] = packff(base[0], base[H_ * W_]);
}

// issue cp.async for slice s into buffer (s&1); interior only (halo pre-zeroed)
__device__ __forceinline__ void issue_slice(u64* xq, const u64* xp,
                                            int q0, int s, int h0, int tid)
{
    const int buf = s & 1;
    for (int i = tid; i < SLICE_Q * XS_ROWS * 16; i += THREADS) {   // 640 chunks
        const int ql = i / (XS_ROWS * 16);
        const int j  = i - ql * (XS_ROWS * 16);
        const int r  = j / 16;
        const int k  = j - r * 16;
        const int gh = h0 + r - 1;
        if ((unsigned)gh < (unsigned)H_) {
            u64* dst = &xq[2 + buf * BUFSZ + ql * PLANE + r * XS_COLS + 2 * k];
            unsigned int da = (unsigned int)__cvta_generic_to_shared(dst);
            cp_async16(da, xp + (size_t)(q0 + s * SLICE_Q + ql) * (H_ * W_) + gh * W_ + 2 * k);
        }
    }
    asm volatile("cp.async.commit_group;\n" ::: "memory");
}

// ---------------- main kernel ----------------
__global__ void __launch_bounds__(THREADS, 7)
adder2d_kernel(const float* __restrict__ w,
               float* __restrict__ out)
{
    // 2 packed-x buffers; LEAD=1 so interior (col>=1) 16B chunks are aligned. 21.8KB
    __shared__ u64 xq[2 * BUFSZ + 2];
    // all 4 slices' weights: [slice][q][tap][co], co contiguous, 16B aligned. 9.2KB
    __shared__ __align__(16) u64 ws2[NSLICE][SLICE_Q][9][CO_T];

    const int tid = threadIdx.x;
    const int tx  = tid & 31;
    const int ty  = tid >> 5;
    const int h0  = blockIdx.x * TILE_H;
    const int co0 = blockIdx.y * CO_T;
    const int n   = blockIdx.z >> 1;
    const int q0  = (blockIdx.z & 1) * (SLICE_Q * NSLICE);   // first ci-pair index

    const u64* xp = xpack_buf + (size_t)n * (CI_ / 2) * (H_ * W_);

    // ---- zero halo in BOTH buffers (cells cp.async never writes stay zero) ----
    for (int i = tid; i < 2 * SLICE_Q * XS_ROWS; i += THREADS) {   // 80 rows
        const int b  = i / (SLICE_Q * XS_ROWS);
        const int j  = i - b * (SLICE_Q * XS_ROWS);
        const int ql = j / XS_ROWS;
        const int r  = j - ql * XS_ROWS;
        u64* row = &xq[1 + b * BUFSZ + ql * PLANE + r * XS_COLS];
        const int gh = h0 + r - 1;
        if ((unsigned)gh >= (unsigned)H_) {
            #pragma unroll
            for (int c = 0; c < XS_COLS; ++c) row[c] = 0ull;
        } else {
            row[0] = 0ull;
            row[XS_COLS - 1] = 0ull;
        }
    }
    __syncthreads();   // halo zeros visible before any cp.async completes into buffers

    // ---- prologue: prefetch slices 0 and 1 ----
    issue_slice(xq, xp, q0, 0, h0, tid);
    issue_slice(xq, xp, q0, 1, h0, tid);

    // ---- stage ALL w (overlaps cp.async latency): 1152 entries ----
    for (int i = tid; i < NSLICE * SLICE_Q * 9 * CO_T; i += THREADS) {
        const int s  = i / (SLICE_Q * 9 * CO_T);
        const int r1 = i - s * (SLICE_Q * 9 * CO_T);
        const int ql = r1 / (9 * CO_T);
        const int r2 = r1 - ql * (9 * CO_T);
        const int tap = r2 / CO_T;
        const int co  = r2 - tap * CO_T;
        const int cib = 2 * (q0 + s * SLICE_Q + ql);
        const float w0 = w[(co0 + co) * (CI_ * 9) + (cib + 0) * 9 + tap];
        const float w1 = w[(co0 + co) * (CI_ * 9) + (cib + 1) * 9 + tap];
        ws2[s][ql][tap][co] = packff(-w0, -w1);
    }

    // accumulators: [pixel-row(2)][co(8)], halves = even/odd ci partial sums
    u64 acc[2][CO_T];
    #pragma unroll
    for (int p = 0; p < 2; ++p)
        #pragma unroll
        for (int co = 0; co < CO_T; ++co) acc[p][co] = 0ull;

    const int px = tx;
    const int ry = 2 * ty;

    #pragma unroll 1
    for (int s = 0; s < NSLICE; ++s) {
        // slice s's group done (at most 1 newer group still pending)
        if (s + 1 < NSLICE) asm volatile("cp.async.wait_group 1;\n" ::: "memory");
        else                asm volatile("cp.async.wait_group 0;\n" ::: "memory");
        __syncthreads();

        const int xb = 1 + (s & 1) * BUFSZ;
        #pragma unroll 2
        for (int ql = 0; ql < SLICE_Q; ++ql) {
            const int pb = xb + ql * PLANE;
            #pragma unroll
            for (int kh = 0; kh < 3; ++kh) {
                #pragma unroll
                for (int kw = 0; kw < 3; ++kw) {
                    const u64 x0 = xq[pb + (ry + 0 + kh) * XS_COLS + px + kw];  // LDS.64
                    const u64 x1 = xq[pb + (ry + 1 + kh) * XS_COLS + px + kw];  // LDS.64
                    const int tap = kh * 3 + kw;
                    #pragma unroll
                    for (int cp = 0; cp < CO_T / 2; ++cp) {
                        const ulonglong2 wv = *(const ulonglong2*)&ws2[s][ql][tap][2 * cp];
                        u64 d0 = f2add(x0, wv.x);               // fma pipe
                        u64 d1 = f2add(x1, wv.x);
                        d0 &= 0x7fffffff7fffffffULL;            // alu pipe (2x LOP3)
                        d1 &= 0x7fffffff7fffffffULL;
                        acc[0][2 * cp + 0] = f2add(acc[0][2 * cp + 0], d0);
                        acc[1][2 * cp + 0] = f2add(acc[1][2 * cp + 0], d1);
                        u64 e0 = f2add(x0, wv.y);
                        u64 e1 = f2add(x1, wv.y);
                        e0 &= 0x7fffffff7fffffffULL;
                        e1 &= 0x7fffffff7fffffffULL;
                        acc[0][2 * cp + 1] = f2add(acc[0][2 * cp + 1], e0);
                        acc[1][2 * cp + 1] = f2add(acc[1][2 * cp + 1], e1);
                    }
                }
            }
        }

        // refill the buffer we just finished reading with slice s+2
        if (s + 2 < NSLICE) {
            __syncthreads();   // all warps done reading buf(s&1)
            issue_slice(xq, xp, q0, s + 2, h0, tid);
        }
    }

    // ---- epilogue: horizontal add (even+odd ci), atomic combine (out pre-zeroed) ----
    #pragma unroll
    for (int co = 0; co < CO_T; ++co) {
        #pragma unroll
        for (int p = 0; p < 2; ++p) {
            const float ssum = u64lo(acc[p][co]) + u64hi(acc[p][co]);
            const int h = h0 + ry + p;
            atomicAdd(&out[(((size_t)n * CO_ + (co0 + co)) * H_ + h) * W_ + px], -ssum);
        }
    }
}

extern "C" void kernel_launch(void* const* d_in, const int* in_sizes, int n_in,
                              void* d_out, int out_size)
{
    const float* x = (const float*)d_in[0];
    const float* w = (const float*)d_in[1];
    float* out = (float*)d_out;

    const int N = in_sizes[0] / (CI_ * H_ * W_);   // 16
    const int total = N * (CI_ / 2) * H_ * W_;     // 524288 packed pairs

    cudaMemsetAsync(d_out, 0, (size_t)out_size * sizeof(float));
    pack_kernel<<<(total + 255) / 256, 256>>>(x, total);

    dim3 grid(H_ / TILE_H, CO_ / CO_T, N * 2);     // (4, 8, 32) = 1024 blocks, one wave
    adder2d_kernel<<<grid, THREADS>>>(w, out);
}